// round 16
// baseline (speedup 1.0000x reference)
#include <cuda_runtime.h>
#include <cuda_fp16.h>
#include <math.h>
#include <stdint.h>
#include <string.h>

#define D_MODEL 256
#define NH 8
#define NL 4
#define NP 4
#define DHEAD 32
#define BATCH 2
#define MAX_M 40960   // >= BATCH * Lq = 39894

// Scratch (static device globals -- no allocation at runtime)
__device__ __half g_valh[(size_t)MAX_M * D_MODEL];   // value, fp16 (N,H,Lv,Dh)
__device__ __half g_qh  [(size_t)MAX_M * D_MODEL];   // query, fp16
__device__ __half g_xh  [(size_t)MAX_M * D_MODEL];   // input_flatten, fp16
__device__ __half g_acch[(size_t)MAX_M * D_MODEL];   // sampled acc, fp16
__device__ __half g_offh[(size_t)MAX_M * D_MODEL];   // sampling offsets, fp16
__device__ float  g_attn[(size_t)MAX_M * (NH*NL*NP)];// logits (N,Lq,H,16) f32
__device__ __half g_Whv [256 * 256];                 // W_val fp16
__device__ __half g_Who [256 * 256];                 // W_out fp16
__device__ __half g_Whqk[384 * 256];                 // W_samp ++ W_attn fp16
__device__ float  g_bqk [384];

// ---------------------------------------------------------------------------
// helpers
// ---------------------------------------------------------------------------
__device__ __forceinline__ uint32_t s_addr(const void* p) {
    uint32_t a;
    asm("{ .reg .u64 t; cvta.to.shared.u64 t, %1; cvt.u32.u64 %0, t; }" : "=r"(a) : "l"(p));
    return a;
}
__device__ __forceinline__ void cp16(uint32_t dst, const void* src) {
    asm volatile("cp.async.ca.shared.global [%0], [%1], 16;" :: "r"(dst), "l"(src));
}
#define CP_COMMIT() asm volatile("cp.async.commit_group;" ::: "memory")
#define CP_WAIT(n)  asm volatile("cp.async.wait_group %0;" :: "n"(n) : "memory")

__device__ __forceinline__ void ldsm_x4(uint32_t& r0, uint32_t& r1, uint32_t& r2, uint32_t& r3,
                                        uint32_t addr) {
    asm volatile("ldmatrix.sync.aligned.m8n8.x4.shared.b16 {%0,%1,%2,%3}, [%4];"
                 : "=r"(r0), "=r"(r1), "=r"(r2), "=r"(r3) : "r"(addr));
}
__device__ __forceinline__ void mma_f16(float* c, const uint32_t* a, const uint32_t* b) {
    asm volatile(
        "mma.sync.aligned.m16n8k16.row.col.f32.f16.f16.f32 "
        "{%0,%1,%2,%3}, {%4,%5,%6,%7}, {%8,%9}, {%0,%1,%2,%3};"
        : "+f"(c[0]), "+f"(c[1]), "+f"(c[2]), "+f"(c[3])
        : "r"(a[0]), "r"(a[1]), "r"(a[2]), "r"(a[3]), "r"(b[0]), "r"(b[1]));
}
__device__ __forceinline__ uint32_t h2u(float x, float y) {
    const __half2 h = __float22half2_rn(make_float2(x, y));
    uint32_t u;
    memcpy(&u, &h, 4);
    return u;
}
__device__ __forceinline__ __half2 u2h2(uint32_t u) {
    __half2 h;
    memcpy(&h, &u, 4);
    return h;
}

// ---------------------------------------------------------------------------
// One-shot prep: fp32->fp16 for query/xin/W_val/W_out/W_samp/W_attn + biases
// ---------------------------------------------------------------------------
__global__ void prep(const float* __restrict__ q,  const float* __restrict__ x,
                     const float* __restrict__ Wv, const float* __restrict__ Wo,
                     const float* __restrict__ Ws, const float* __restrict__ bs,
                     const float* __restrict__ Wa, const float* __restrict__ ba,
                     int n4)
{
    const int tid0 = blockIdx.x * blockDim.x + threadIdx.x;
    if (tid0 < 256)       g_bqk[tid0] = bs[tid0];
    else if (tid0 < 384)  g_bqk[tid0] = ba[tid0 - 256];

    const int total = 2 * n4 + 3 * 16384 + 8192;
    const int stride = gridDim.x * blockDim.x;
    for (int i = tid0; i < total; i += stride) {
        int j = i;
        const float4* src;
        uint2* dst;
        if (j < n4)                        { src = (const float4*)q;  dst = (uint2*)g_qh; }
        else if ((j -= n4) < n4)           { src = (const float4*)x;  dst = (uint2*)g_xh; }
        else if ((j -= n4) < 16384)        { src = (const float4*)Wv; dst = (uint2*)g_Whv; }
        else if ((j -= 16384) < 16384)     { src = (const float4*)Wo; dst = (uint2*)g_Who; }
        else if ((j -= 16384) < 16384)     { src = (const float4*)Ws; dst = (uint2*)g_Whqk; }
        else { j -= 16384;                   src = (const float4*)Wa; dst = (uint2*)g_Whqk + 16384; }
        const float4 v = src[j];
        uint2 u;
        u.x = h2u(v.x, v.y);
        u.y = h2u(v.z, v.w);
        dst[j] = u;
    }
}

// ---------------------------------------------------------------------------
// FP16 mma.sync GEMM core (fp32 accum), 2-stage cp.async, BKK=64 (4 K-iters).
// ---------------------------------------------------------------------------
#define BM 128
#define BN 128
#define BKK 64
#define PADH 8
#define ROWH (BKK + PADH)          // 72 halves = 144 bytes (16B-multiple)

struct GemmCtx {
    __half As[2][BM][ROWH];
    __half Bs[2][BN][ROWH];
};
#define GEMM_SMEM ((int)sizeof(GemmCtx))   // 73728 bytes

// Loader: thread -> row (tid>>1), 64-byte half (tid&1); 4 x 16B chunks per
// matrix per tile. 256 threads cover 128 rows x 128 bytes exactly once.
__device__ __forceinline__ void gemm_issue(const __half* Abase, const __half* Wbase,
                                           uint32_t aDst, uint32_t bDst, int kt,
                                           int r0, int colh)
{
#pragma unroll
    for (int k = 0; k < 4; k++) {
        cp16(aDst + r0 * 144 + colh * 64 + k * 16, Abase + (size_t)r0 * 256 + kt + colh * 32 + k * 8);
        cp16(bDst + r0 * 144 + colh * 64 + k * 16, Wbase + (size_t)r0 * 256 + kt + colh * 32 + k * 8);
    }
    CP_COMMIT();
}

__device__ __forceinline__ void gemm_main(const __half* __restrict__ A,
                                          const __half* __restrict__ W,
                                          int brow, int bcol, GemmCtx* sm,
                                          float acc[4][4][4])
{
    const int tid  = threadIdx.x;
    const int lane = tid & 31;
    const int warp = tid >> 5;
    const int wm   = (warp & 1) * 64;
    const int wn   = (warp >> 1) * 32;

    const int r0   = tid >> 1;
    const int colh = tid & 1;

    const uint32_t sA0 = s_addr(&sm->As[0][0][0]);
    const uint32_t sB0 = s_addr(&sm->Bs[0][0][0]);
    const uint32_t bufBytes = BM * ROWH * 2;

    const int lmRow = lane & 15;
    const int lmSeg = (lane >> 4) * 8;

    const __half* Abase = A + (size_t)brow * 256;
    const __half* Wbase = W + (size_t)bcol * 256;

    gemm_issue(Abase, Wbase, sA0, sB0, 0, r0, colh);

#pragma unroll
    for (int mt = 0; mt < 4; mt++)
#pragma unroll
        for (int nt = 0; nt < 4; nt++)
#pragma unroll
            for (int r = 0; r < 4; r++) acc[mt][nt][r] = 0.f;

#pragma unroll
    for (int t = 0; t < 4; t++) {
        const int cur = t & 1;
        if (t < 3) {
            gemm_issue(Abase, Wbase, sA0 + (cur ^ 1) * bufBytes, sB0 + (cur ^ 1) * bufBytes,
                       (t + 1) * BKK, r0, colh);
            CP_WAIT(1);
        } else {
            CP_WAIT(0);
        }
        __syncthreads();

#pragma unroll
        for (int ks = 0; ks < 4; ks++) {
            const int kb = ks * 16;
            uint32_t af[4][4], bf[4][2];
#pragma unroll
            for (int mt = 0; mt < 4; mt++) {
                const uint32_t ad = s_addr(&sm->As[cur][wm + mt * 16 + lmRow][kb + lmSeg]);
                ldsm_x4(af[mt][0], af[mt][1], af[mt][2], af[mt][3], ad);
            }
#pragma unroll
            for (int nb = 0; nb < 2; nb++) {
                const uint32_t bd = s_addr(&sm->Bs[cur][wn + nb * 16 + lmRow][kb + lmSeg]);
                ldsm_x4(bf[2 * nb][0], bf[2 * nb + 1][0], bf[2 * nb][1], bf[2 * nb + 1][1], bd);
            }
#pragma unroll
            for (int mt = 0; mt < 4; mt++)
#pragma unroll
                for (int nt = 0; nt < 4; nt++)
                    mma_f16(acc[mt][nt], af[mt], bf[nt]);
        }
        __syncthreads();
    }
}

// Merged value + qk projection:
//   grid.y 0..1 -> value GEMM (A=g_xh, W=g_Whv), EPI: fp16 remap to (N,H,Lv,Dh)
//   grid.y 2..4 -> qk GEMM (A=g_qh, W=g_Whqk), EPI: off->fp16, attn->f32
__global__ __launch_bounds__(256)
void hgemm_vqk(const float* __restrict__ bval, float* __restrict__ Cattn, int M, int Lv)
{
    extern __shared__ char dsm[];
    GemmCtx* sm = reinterpret_cast<GemmCtx*>(dsm);
    const int by = blockIdx.y;
    const bool isVal = (by < 2);
    const int bcol = (isVal ? by : by - 2) * BN;
    const int brow = blockIdx.x * BM;

    const __half* A = isVal ? g_xh : g_qh;
    const __half* W = isVal ? g_Whv : g_Whqk;
    const float* bias = isVal ? bval : g_bqk;

    float acc[4][4][4];
    gemm_main(A, W, brow, bcol, sm, acc);

    const int tid  = threadIdx.x;
    const int lane = tid & 31;
    const int warp = tid >> 5;
    const int wm   = (warp & 1) * 64;
    const int wn   = (warp >> 1) * 32;
    const int lr   = lane >> 2;
    const int lc   = lane & 3;

#pragma unroll
    for (int mt = 0; mt < 4; mt++) {
#pragma unroll
        for (int nt = 0; nt < 4; nt++) {
            const int c0 = bcol + wn + nt * 8 + lc * 2;
            const float b0 = __ldg(bias + c0);
            const float b1 = __ldg(bias + c0 + 1);
#pragma unroll
            for (int rr = 0; rr < 2; rr++) {
                const int r = brow + wm + mt * 16 + lr + rr * 8;
                if (r >= M) continue;
                const float v0 = acc[mt][nt][rr * 2 + 0] + b0;
                const float v1 = acc[mt][nt][rr * 2 + 1] + b1;
                if (isVal) {
                    const int nb2 = r / Lv, l = r - nb2 * Lv;
                    const int h = c0 >> 5, dh = c0 & 31;
                    __half* p = g_valh + ((((size_t)(nb2 * NH + h)) * Lv) + l) * DHEAD + dh;
                    *reinterpret_cast<__half2*>(p) = __float22half2_rn(make_float2(v0, v1));
                } else if (c0 < 256) {
                    __half* p = g_offh + (size_t)r * 256 + c0;
                    *reinterpret_cast<__half2*>(p) = __float22half2_rn(make_float2(v0, v1));
                } else {
                    *reinterpret_cast<float2*>(Cattn + (size_t)r * 128 + (c0 - 256)) = make_float2(v0, v1);
                }
            }
        }
    }
}

// Output projection: out[M,256] = acch @ Who^T + b_out (f32 row-major store)
__global__ __launch_bounds__(256)
void hgemm_out(const float* __restrict__ bias, float* __restrict__ C, int M)
{
    extern __shared__ char dsm[];
    GemmCtx* sm = reinterpret_cast<GemmCtx*>(dsm);
    const int brow = blockIdx.x * BM;
    const int bcol = blockIdx.y * BN;

    float acc[4][4][4];
    gemm_main(g_acch, g_Who, brow, bcol, sm, acc);

    const int tid  = threadIdx.x;
    const int lane = tid & 31;
    const int warp = tid >> 5;
    const int wm   = (warp & 1) * 64;
    const int wn   = (warp >> 1) * 32;
    const int lr   = lane >> 2;
    const int lc   = lane & 3;

#pragma unroll
    for (int mt = 0; mt < 4; mt++) {
#pragma unroll
        for (int nt = 0; nt < 4; nt++) {
            const int c0 = bcol + wn + nt * 8 + lc * 2;
            const float b0 = __ldg(bias + c0);
            const float b1 = __ldg(bias + c0 + 1);
#pragma unroll
            for (int rr = 0; rr < 2; rr++) {
                const int r = brow + wm + mt * 16 + lr + rr * 8;
                if (r >= M) continue;
                *reinterpret_cast<float2*>(C + (size_t)r * 256 + c0) =
                    make_float2(acc[mt][nt][rr * 2 + 0] + b0, acc[mt][nt][rr * 2 + 1] + b1);
            }
        }
    }
}

// ---------------------------------------------------------------------------
// Sampling + softmax, two-phase (round-13 version: HFMA2 inner loop).
// ---------------------------------------------------------------------------
__global__ __launch_bounds__(256)
void msda_sample(const float* __restrict__ ref,
                 const int* __restrict__ shapes,
                 const int* __restrict__ lstart,
                 int Lq, int total)
{
    __shared__ int2 s_iw[16][16][4];    // (element offset, half2(w,w) bits)
    __shared__ int  s_vbase[16];

    const int tid = threadIdx.x;

    // ---------------- Phase 1 ----------------
    {
        const int u  = tid >> 4;
        const int pt = tid & 15;
        const int gu = blockIdx.x * 16 + u;
        const bool act = gu < total;

        const int h  = gu & (NH - 1);
        const int mq = gu >> 3;                    // n*Lq + q

        float logit = act ? __ldg(g_attn + (size_t)gu * 16 + pt) : 0.f;
        float mx = logit;
#pragma unroll
        for (int s = 8; s > 0; s >>= 1) mx = fmaxf(mx, __shfl_xor_sync(0xffffffffu, mx, s));
        float e = __expf(logit - mx);
        float sum = e;
#pragma unroll
        for (int s = 8; s > 0; s >>= 1) sum += __shfl_xor_sync(0xffffffffu, sum, s);
        const float aw = e / sum;

        if (act) {
            const int lvl = pt >> 2;
            const int Hl = __ldg(shapes + lvl * 2 + 0);
            const int Wl = __ldg(shapes + lvl * 2 + 1);
            const int st = __ldg(lstart + lvl);

            const float2 rxy = *reinterpret_cast<const float2*>(ref + (size_t)mq * (NL * 2) + lvl * 2);
            const float2 oxy = __half22float2(
                *reinterpret_cast<const __half2*>(g_offh + (size_t)gu * 32 + 2 * pt));

            const float x = fmaf(rxy.x, (float)Wl, oxy.x) - 0.5f;
            const float y = fmaf(rxy.y, (float)Hl, oxy.y) - 0.5f;
            const float xf = floorf(x), yf = floorf(y);
            const float lx = x - xf, ly = y - yf;
            const int x0 = (int)xf, y0 = (int)yf;
            const int x1 = x0 + 1,  y1 = y0 + 1;

            const float vx0 = (x0 >= 0 && x0 < Wl) ? 1.f : 0.f;
            const float vx1 = (x1 >= 0 && x1 < Wl) ? 1.f : 0.f;
            const float vy0 = (y0 >= 0 && y0 < Hl) ? 1.f : 0.f;
            const float vy1 = (y1 >= 0 && y1 < Hl) ? 1.f : 0.f;

            const int x0c = min(max(x0, 0), Wl - 1);
            const int x1c = min(max(x1, 0), Wl - 1);
            const int y0c = min(max(y0, 0), Hl - 1);
            const int y1c = min(max(y1, 0), Hl - 1);

            const int r0 = (st + y0c * Wl) * DHEAD;
            const int r1 = (st + y1c * Wl) * DHEAD;
            const float w00 = aw * (1.f - lx) * (1.f - ly) * vx0 * vy0;
            const float w01 = aw * (1.f - lx) * ly * vx0 * vy1;
            const float w10 = aw * lx * (1.f - ly) * vx1 * vy0;
            const float w11 = aw * lx * ly * vx1 * vy1;

            // corner order: [x0y0, x0y1, x1y0, x1y1]; weight as half2(w,w)
            s_iw[u][pt][0] = make_int2(r0 + x0c * DHEAD, (int)h2u(w00, w00));
            s_iw[u][pt][1] = make_int2(r1 + x0c * DHEAD, (int)h2u(w01, w01));
            s_iw[u][pt][2] = make_int2(r0 + x1c * DHEAD, (int)h2u(w10, w10));
            s_iw[u][pt][3] = make_int2(r1 + x1c * DHEAD, (int)h2u(w11, w11));

            if (pt == 0) {
                const int n = mq / Lq;
                s_vbase[u] = ((n * NH + h) * Lq) * DHEAD;
            }
        }
    }
    __syncthreads();

    // ---------------- Phase 2 ----------------
    {
        const int warp   = tid >> 5;
        const int lane   = tid & 31;
        const int corner = lane >> 3;     // 0..3
        const int cq     = lane & 7;      // channel quad (4 channels)
#pragma unroll
        for (int uu = 0; uu < 2; uu++) {
            const int u  = warp * 2 + uu;
            const int gu = blockIdx.x * 16 + u;
            if (gu >= total) continue;

            const __half* bp = g_valh + s_vbase[u] + cq * 4;
            float a0 = 0.f, a1 = 0.f, a2 = 0.f, a3 = 0.f;
#pragma unroll
            for (int g = 0; g < 4; g++) {
                __half2 h0 = __float2half2_rn(0.f);
                __half2 h1 = __float2half2_rn(0.f);
#pragma unroll
                for (int k = 0; k < 4; k++) {
                    const int2  iw = s_iw[u][g * 4 + k][corner];
                    const __half2 wh = u2h2((uint32_t)iw.y);
                    const uint2 v  = *reinterpret_cast<const uint2*>(bp + iw.x);
                    h0 = __hfma2(wh, u2h2(v.x), h0);
                    h1 = __hfma2(wh, u2h2(v.y), h1);
                }
                const float2 f0 = __half22float2(h0);
                const float2 f1 = __half22float2(h1);
                a0 += f0.x; a1 += f0.y; a2 += f1.x; a3 += f1.y;
            }
            a0 += __shfl_xor_sync(0xffffffffu, a0, 8);
            a1 += __shfl_xor_sync(0xffffffffu, a1, 8);
            a2 += __shfl_xor_sync(0xffffffffu, a2, 8);
            a3 += __shfl_xor_sync(0xffffffffu, a3, 8);
            a0 += __shfl_xor_sync(0xffffffffu, a0, 16);
            a1 += __shfl_xor_sync(0xffffffffu, a1, 16);
            a2 += __shfl_xor_sync(0xffffffffu, a2, 16);
            a3 += __shfl_xor_sync(0xffffffffu, a3, 16);
            if (lane < 8) {
                uint2 u2;
                u2.x = h2u(a0, a1);
                u2.y = h2u(a2, a3);
                *reinterpret_cast<uint2*>(g_acch + (size_t)gu * DHEAD + cq * 4) = u2;
            }
        }
    }
}

// ---------------------------------------------------------------------------
// Launch
// ---------------------------------------------------------------------------
extern "C" void kernel_launch(void* const* d_in, const int* in_sizes, int n_in,
                              void* d_out, int out_size)
{
    const float* query  = (const float*)d_in[0];
    const float* refp   = (const float*)d_in[1];
    const float* xin    = (const float*)d_in[2];
    const int*   shapes = (const int*)  d_in[3];
    const int*   lstart = (const int*)  d_in[4];
    const float* W_samp = (const float*)d_in[5];
    const float* b_samp = (const float*)d_in[6];
    const float* W_attn = (const float*)d_in[7];
    const float* b_attn = (const float*)d_in[8];
    const float* W_val  = (const float*)d_in[9];
    const float* b_val  = (const float*)d_in[10];
    const float* W_out  = (const float*)d_in[11];
    const float* b_out  = (const float*)d_in[12];
    float* out = (float*)d_out;

    const int Lq = in_sizes[0] / (BATCH * D_MODEL);
    const int M  = BATCH * Lq;

    void* pa;
    cudaGetSymbolAddress(&pa, g_attn);

    static bool attrSet = false;
    if (!attrSet) {
        cudaFuncSetAttribute(hgemm_vqk, cudaFuncAttributeMaxDynamicSharedMemorySize, GEMM_SMEM);
        cudaFuncSetAttribute(hgemm_out, cudaFuncAttributeMaxDynamicSharedMemorySize, GEMM_SMEM);
        attrSet = true;
    }

    const int gx = (M + BM - 1) / BM;
    dim3 blk(256);
    const int n4 = M * 64;                   // M*256/4

    // 0) one-shot fp16 conversion + weight pack
    prep<<<1024, blk>>>(query, xin, W_val, W_out, W_samp, b_samp, W_attn, b_attn, n4);
    // 1) merged value + qk projection (value->fp16 remap; off->fp16; attn->f32)
    hgemm_vqk<<<dim3(gx, 5), blk, GEMM_SMEM>>>(b_val, (float*)pa, M, Lq);
    // 2) softmax + deformable sampling (writes fp16 acc)
    {
        const int total = M * NH;
        const int nblk  = (total + 15) / 16;
        msda_sample<<<nblk, blk>>>(refp, shapes, lstart, Lq, total);
    }
    // 3) output projection
    hgemm_out<<<dim3(gx, 2), blk, GEMM_SMEM>>>(b_out, out, M);
}

// round 17
// speedup vs baseline: 1.1678x; 1.1678x over previous
#include <cuda_runtime.h>
#include <cuda_fp16.h>
#include <math.h>
#include <stdint.h>
#include <string.h>

#define D_MODEL 256
#define NH 8
#define NL 4
#define NP 4
#define DHEAD 32
#define BATCH 2
#define MAX_M 40960   // >= BATCH * Lq = 39894

// Scratch (static device globals -- no allocation at runtime)
__device__ __half g_valh[(size_t)MAX_M * D_MODEL];   // value, fp16 (N,H,Lv,Dh)
__device__ __half g_qh  [(size_t)MAX_M * D_MODEL];   // query, fp16
__device__ __half g_xh  [(size_t)MAX_M * D_MODEL];   // input_flatten, fp16
__device__ __half g_acch[(size_t)MAX_M * D_MODEL];   // sampled acc, fp16
__device__ __half g_offh[(size_t)MAX_M * D_MODEL];   // sampling offsets, fp16
__device__ float  g_attn[(size_t)MAX_M * (NH*NL*NP)];// logits (N,Lq,H,16) f32
__device__ __half g_Whv [256 * 256];                 // W_val fp16
__device__ __half g_Who [256 * 256];                 // W_out fp16
__device__ __half g_Whqk[384 * 256];                 // W_samp ++ W_attn fp16
__device__ float  g_bqk [384];

// ---------------------------------------------------------------------------
// helpers
// ---------------------------------------------------------------------------
__device__ __forceinline__ uint32_t s_addr(const void* p) {
    uint32_t a;
    asm("{ .reg .u64 t; cvta.to.shared.u64 t, %1; cvt.u32.u64 %0, t; }" : "=r"(a) : "l"(p));
    return a;
}
__device__ __forceinline__ void cp16(uint32_t dst, const void* src) {
    asm volatile("cp.async.ca.shared.global [%0], [%1], 16;" :: "r"(dst), "l"(src));
}
#define CP_COMMIT() asm volatile("cp.async.commit_group;" ::: "memory")
#define CP_WAIT(n)  asm volatile("cp.async.wait_group %0;" :: "n"(n) : "memory")

__device__ __forceinline__ void ldsm_x4(uint32_t& r0, uint32_t& r1, uint32_t& r2, uint32_t& r3,
                                        uint32_t addr) {
    asm volatile("ldmatrix.sync.aligned.m8n8.x4.shared.b16 {%0,%1,%2,%3}, [%4];"
                 : "=r"(r0), "=r"(r1), "=r"(r2), "=r"(r3) : "r"(addr));
}
__device__ __forceinline__ void mma_f16(float* c, const uint32_t* a, const uint32_t* b) {
    asm volatile(
        "mma.sync.aligned.m16n8k16.row.col.f32.f16.f16.f32 "
        "{%0,%1,%2,%3}, {%4,%5,%6,%7}, {%8,%9}, {%0,%1,%2,%3};"
        : "+f"(c[0]), "+f"(c[1]), "+f"(c[2]), "+f"(c[3])
        : "r"(a[0]), "r"(a[1]), "r"(a[2]), "r"(a[3]), "r"(b[0]), "r"(b[1]));
}
__device__ __forceinline__ uint32_t h2u(float x, float y) {
    const __half2 h = __float22half2_rn(make_float2(x, y));
    uint32_t u;
    memcpy(&u, &h, 4);
    return u;
}
__device__ __forceinline__ __half2 u2h2(uint32_t u) {
    __half2 h;
    memcpy(&h, &u, 4);
    return h;
}

// ---------------------------------------------------------------------------
// One-shot prep: fp32->fp16 for query/xin/W_val/W_out/W_samp/W_attn + biases
// ---------------------------------------------------------------------------
__global__ void prep(const float* __restrict__ q,  const float* __restrict__ x,
                     const float* __restrict__ Wv, const float* __restrict__ Wo,
                     const float* __restrict__ Ws, const float* __restrict__ bs,
                     const float* __restrict__ Wa, const float* __restrict__ ba,
                     int n4)
{
    const int tid0 = blockIdx.x * blockDim.x + threadIdx.x;
    if (tid0 < 256)       g_bqk[tid0] = bs[tid0];
    else if (tid0 < 384)  g_bqk[tid0] = ba[tid0 - 256];

    const int total = 2 * n4 + 3 * 16384 + 8192;
    const int stride = gridDim.x * blockDim.x;
    for (int i = tid0; i < total; i += stride) {
        int j = i;
        const float4* src;
        uint2* dst;
        if (j < n4)                        { src = (const float4*)q;  dst = (uint2*)g_qh; }
        else if ((j -= n4) < n4)           { src = (const float4*)x;  dst = (uint2*)g_xh; }
        else if ((j -= n4) < 16384)        { src = (const float4*)Wv; dst = (uint2*)g_Whv; }
        else if ((j -= 16384) < 16384)     { src = (const float4*)Wo; dst = (uint2*)g_Who; }
        else if ((j -= 16384) < 16384)     { src = (const float4*)Ws; dst = (uint2*)g_Whqk; }
        else { j -= 16384;                   src = (const float4*)Wa; dst = (uint2*)g_Whqk + 16384; }
        const float4 v = src[j];
        uint2 u;
        u.x = h2u(v.x, v.y);
        u.y = h2u(v.z, v.w);
        dst[j] = u;
    }
}

// ---------------------------------------------------------------------------
// FP16 mma.sync GEMM core (fp32 accum), 2-stage cp.async, BKK=32 (round-13).
// ---------------------------------------------------------------------------
#define BM 128
#define BN 128
#define BKK 32
#define PADH 8
#define ROWH (BKK + PADH)          // 40 halves = 80 bytes

struct GemmCtx {
    __half As[2][BM][ROWH];
    __half Bs[2][BN][ROWH];
};

__device__ __forceinline__ void gemm_main(const __half* __restrict__ A,
                                          const __half* __restrict__ W,
                                          int brow, int bcol, GemmCtx* sm,
                                          float acc[4][4][4])
{
    const int tid  = threadIdx.x;
    const int lane = tid & 31;
    const int warp = tid >> 5;
    const int wm   = (warp & 1) * 64;
    const int wn   = (warp >> 1) * 32;
    const int K = 256;

    const int c0r = tid >> 2,  c0c = tid & 3;
    const int c1r = 64 + c0r;
    const uint32_t sA0 = s_addr(&sm->As[0][0][0]);
    const uint32_t sB0 = s_addr(&sm->Bs[0][0][0]);
    const uint32_t bufBytes = BM * ROWH * 2;

    const int lmRow = lane & 15;
    const int lmSeg = (lane >> 4) * 8;

    const __half* Abase = A + (size_t)brow * K;
    const __half* Wbase = W + (size_t)bcol * K;

    cp16(sA0 + c0r * 80 + c0c * 16, Abase + (size_t)c0r * K + c0c * 8);
    cp16(sA0 + c1r * 80 + c0c * 16, Abase + (size_t)c1r * K + c0c * 8);
    cp16(sB0 + c0r * 80 + c0c * 16, Wbase + (size_t)c0r * K + c0c * 8);
    cp16(sB0 + c1r * 80 + c0c * 16, Wbase + (size_t)c1r * K + c0c * 8);
    CP_COMMIT();

#pragma unroll
    for (int mt = 0; mt < 4; mt++)
#pragma unroll
        for (int nt = 0; nt < 4; nt++)
#pragma unroll
            for (int r = 0; r < 4; r++) acc[mt][nt][r] = 0.f;

#pragma unroll
    for (int t = 0; t < 8; t++) {
        const int cur = t & 1;
        if (t < 7) {
            const int kt = (t + 1) * BKK;
            const uint32_t dA = sA0 + (cur ^ 1) * bufBytes;
            const uint32_t dB = sB0 + (cur ^ 1) * bufBytes;
            cp16(dA + c0r * 80 + c0c * 16, Abase + (size_t)c0r * K + kt + c0c * 8);
            cp16(dA + c1r * 80 + c0c * 16, Abase + (size_t)c1r * K + kt + c0c * 8);
            cp16(dB + c0r * 80 + c0c * 16, Wbase + (size_t)c0r * K + kt + c0c * 8);
            cp16(dB + c1r * 80 + c0c * 16, Wbase + (size_t)c1r * K + kt + c0c * 8);
            CP_COMMIT();
            CP_WAIT(1);
        } else {
            CP_WAIT(0);
        }
        __syncthreads();

#pragma unroll
        for (int ks = 0; ks < 2; ks++) {
            const int kb = ks * 16;
            uint32_t af[4][4], bf[4][2];
#pragma unroll
            for (int mt = 0; mt < 4; mt++) {
                const uint32_t ad = s_addr(&sm->As[cur][wm + mt * 16 + lmRow][kb + lmSeg]);
                ldsm_x4(af[mt][0], af[mt][1], af[mt][2], af[mt][3], ad);
            }
#pragma unroll
            for (int nb = 0; nb < 2; nb++) {
                const uint32_t bd = s_addr(&sm->Bs[cur][wn + nb * 16 + lmRow][kb + lmSeg]);
                ldsm_x4(bf[2 * nb][0], bf[2 * nb + 1][0], bf[2 * nb][1], bf[2 * nb + 1][1], bd);
            }
#pragma unroll
            for (int mt = 0; mt < 4; mt++)
#pragma unroll
                for (int nt = 0; nt < 4; nt++)
                    mma_f16(acc[mt][nt], af[mt], bf[nt]);
        }
        __syncthreads();
    }
}

// Merged value + qk projection:
//   grid.y 0..1 -> value GEMM (A=g_xh, W=g_Whv), EPI: fp16 remap to (N,H,Lv,Dh)
//   grid.y 2..4 -> qk GEMM (A=g_qh, W=g_Whqk), EPI: off->fp16, attn->f32
__global__ __launch_bounds__(256)
void hgemm_vqk(const float* __restrict__ bval, float* __restrict__ Cattn, int M, int Lv)
{
    __shared__ GemmCtx sm;
    const int by = blockIdx.y;
    const bool isVal = (by < 2);
    const int bcol = (isVal ? by : by - 2) * BN;
    const int brow = blockIdx.x * BM;

    const __half* A = isVal ? g_xh : g_qh;
    const __half* W = isVal ? g_Whv : g_Whqk;
    const float* bias = isVal ? bval : g_bqk;

    float acc[4][4][4];
    gemm_main(A, W, brow, bcol, &sm, acc);

    const int tid  = threadIdx.x;
    const int lane = tid & 31;
    const int warp = tid >> 5;
    const int wm   = (warp & 1) * 64;
    const int wn   = (warp >> 1) * 32;
    const int lr   = lane >> 2;
    const int lc   = lane & 3;

#pragma unroll
    for (int mt = 0; mt < 4; mt++) {
#pragma unroll
        for (int nt = 0; nt < 4; nt++) {
            const int c0 = bcol + wn + nt * 8 + lc * 2;
            const float b0 = __ldg(bias + c0);
            const float b1 = __ldg(bias + c0 + 1);
#pragma unroll
            for (int rr = 0; rr < 2; rr++) {
                const int r = brow + wm + mt * 16 + lr + rr * 8;
                if (r >= M) continue;
                const float v0 = acc[mt][nt][rr * 2 + 0] + b0;
                const float v1 = acc[mt][nt][rr * 2 + 1] + b1;
                if (isVal) {
                    const int nb2 = r / Lv, l = r - nb2 * Lv;
                    const int h = c0 >> 5, dh = c0 & 31;
                    __half* p = g_valh + ((((size_t)(nb2 * NH + h)) * Lv) + l) * DHEAD + dh;
                    *reinterpret_cast<__half2*>(p) = __float22half2_rn(make_float2(v0, v1));
                } else if (c0 < 256) {
                    __half* p = g_offh + (size_t)r * 256 + c0;
                    *reinterpret_cast<__half2*>(p) = __float22half2_rn(make_float2(v0, v1));
                } else {
                    *reinterpret_cast<float2*>(Cattn + (size_t)r * 128 + (c0 - 256)) = make_float2(v0, v1);
                }
            }
        }
    }
}

// Output projection: out[M,256] = acch @ Who^T + b_out (f32 row-major store)
__global__ __launch_bounds__(256)
void hgemm_out(const float* __restrict__ bias, float* __restrict__ C, int M)
{
    __shared__ GemmCtx sm;
    const int brow = blockIdx.x * BM;
    const int bcol = blockIdx.y * BN;

    float acc[4][4][4];
    gemm_main(g_acch, g_Who, brow, bcol, &sm, acc);

    const int tid  = threadIdx.x;
    const int lane = tid & 31;
    const int warp = tid >> 5;
    const int wm   = (warp & 1) * 64;
    const int wn   = (warp >> 1) * 32;
    const int lr   = lane >> 2;
    const int lc   = lane & 3;

#pragma unroll
    for (int mt = 0; mt < 4; mt++) {
#pragma unroll
        for (int nt = 0; nt < 4; nt++) {
            const int c0 = bcol + wn + nt * 8 + lc * 2;
            const float b0 = __ldg(bias + c0);
            const float b1 = __ldg(bias + c0 + 1);
#pragma unroll
            for (int rr = 0; rr < 2; rr++) {
                const int r = brow + wm + mt * 16 + lr + rr * 8;
                if (r >= M) continue;
                *reinterpret_cast<float2*>(C + (size_t)r * 256 + c0) =
                    make_float2(acc[mt][nt][rr * 2 + 0] + b0, acc[mt][nt][rr * 2 + 1] + b1);
            }
        }
    }
}

// ---------------------------------------------------------------------------
// Sampling + softmax, two-phase.
// Phase 1 packs per (pt, y-corner): int4 { idx_x0, idx_x1, w_x0(h2), w_x1(h2) }.
// Phase 2: lane = (y[1b], x[1b], cq[3b]); per pt: broadcast LDS.128 + select +
// LDG.64; the 16 lanes of a y-group touch x0||x1 contiguously (1-2 lines vs 2).
// Reduction: shfl_xor(8) merges x, shfl_xor(16) merges y.
// ---------------------------------------------------------------------------
__global__ __launch_bounds__(256)
void msda_sample(const float* __restrict__ ref,
                 const int* __restrict__ shapes,
                 const int* __restrict__ lstart,
                 int Lq, int total)
{
    __shared__ int4 s_iw[16][16][2];    // [unit][pt][y]: idx_x0, idx_x1, w_x0, w_x1
    __shared__ int  s_vbase[16];

    const int tid = threadIdx.x;

    // ---------------- Phase 1 ----------------
    {
        const int u  = tid >> 4;
        const int pt = tid & 15;
        const int gu = blockIdx.x * 16 + u;
        const bool act = gu < total;

        const int h  = gu & (NH - 1);
        const int mq = gu >> 3;                    // n*Lq + q

        float logit = act ? __ldg(g_attn + (size_t)gu * 16 + pt) : 0.f;
        float mx = logit;
#pragma unroll
        for (int s = 8; s > 0; s >>= 1) mx = fmaxf(mx, __shfl_xor_sync(0xffffffffu, mx, s));
        float e = __expf(logit - mx);
        float sum = e;
#pragma unroll
        for (int s = 8; s > 0; s >>= 1) sum += __shfl_xor_sync(0xffffffffu, sum, s);
        const float aw = e / sum;

        if (act) {
            const int lvl = pt >> 2;
            const int Hl = __ldg(shapes + lvl * 2 + 0);
            const int Wl = __ldg(shapes + lvl * 2 + 1);
            const int st = __ldg(lstart + lvl);

            const float2 rxy = *reinterpret_cast<const float2*>(ref + (size_t)mq * (NL * 2) + lvl * 2);
            const float2 oxy = __half22float2(
                *reinterpret_cast<const __half2*>(g_offh + (size_t)gu * 32 + 2 * pt));

            const float x = fmaf(rxy.x, (float)Wl, oxy.x) - 0.5f;
            const float y = fmaf(rxy.y, (float)Hl, oxy.y) - 0.5f;
            const float xf = floorf(x), yf = floorf(y);
            const float lx = x - xf, ly = y - yf;
            const int x0 = (int)xf, y0 = (int)yf;
            const int x1 = x0 + 1,  y1 = y0 + 1;

            const float vx0 = (x0 >= 0 && x0 < Wl) ? 1.f : 0.f;
            const float vx1 = (x1 >= 0 && x1 < Wl) ? 1.f : 0.f;
            const float vy0 = (y0 >= 0 && y0 < Hl) ? 1.f : 0.f;
            const float vy1 = (y1 >= 0 && y1 < Hl) ? 1.f : 0.f;

            const int x0c = min(max(x0, 0), Wl - 1);
            const int x1c = min(max(x1, 0), Wl - 1);
            const int y0c = min(max(y0, 0), Hl - 1);
            const int y1c = min(max(y1, 0), Hl - 1);

            const int r0 = (st + y0c * Wl) * DHEAD;
            const int r1 = (st + y1c * Wl) * DHEAD;
            const float w00 = aw * (1.f - lx) * (1.f - ly) * vx0 * vy0;
            const float w01 = aw * (1.f - lx) * ly * vx0 * vy1;
            const float w10 = aw * lx * (1.f - ly) * vx1 * vy0;
            const float w11 = aw * lx * ly * vx1 * vy1;

            s_iw[u][pt][0] = make_int4(r0 + x0c * DHEAD, r0 + x1c * DHEAD,
                                       (int)h2u(w00, w00), (int)h2u(w10, w10));
            s_iw[u][pt][1] = make_int4(r1 + x0c * DHEAD, r1 + x1c * DHEAD,
                                       (int)h2u(w01, w01), (int)h2u(w11, w11));

            if (pt == 0) {
                const int n = mq / Lq;
                s_vbase[u] = ((n * NH + h) * Lq) * DHEAD;
            }
        }
    }
    __syncthreads();

    // ---------------- Phase 2 ----------------
    {
        const int warp = tid >> 5;
        const int lane = tid & 31;
        const int yc   = lane >> 4;       // y corner (0/1)
        const int xc   = (lane >> 3) & 1; // x corner (0/1)
        const int cq   = lane & 7;        // channel quad (4 channels)
#pragma unroll
        for (int uu = 0; uu < 2; uu++) {
            const int u  = warp * 2 + uu;
            const int gu = blockIdx.x * 16 + u;
            if (gu >= total) continue;

            const __half* bp = g_valh + s_vbase[u] + cq * 4;
            float a0 = 0.f, a1 = 0.f, a2 = 0.f, a3 = 0.f;
#pragma unroll
            for (int g = 0; g < 4; g++) {
                __half2 h0 = __float2half2_rn(0.f);
                __half2 h1 = __float2half2_rn(0.f);
#pragma unroll
                for (int k = 0; k < 4; k++) {
                    const int4 iw = s_iw[u][g * 4 + k][yc];
                    const int   idx   = xc ? iw.y : iw.x;
                    const int   wbits = xc ? iw.w : iw.z;
                    const __half2 wh = u2h2((uint32_t)wbits);
                    const uint2 v  = *reinterpret_cast<const uint2*>(bp + idx);
                    h0 = __hfma2(wh, u2h2(v.x), h0);
                    h1 = __hfma2(wh, u2h2(v.y), h1);
                }
                const float2 f0 = __half22float2(h0);
                const float2 f1 = __half22float2(h1);
                a0 += f0.x; a1 += f0.y; a2 += f1.x; a3 += f1.y;
            }
            a0 += __shfl_xor_sync(0xffffffffu, a0, 8);
            a1 += __shfl_xor_sync(0xffffffffu, a1, 8);
            a2 += __shfl_xor_sync(0xffffffffu, a2, 8);
            a3 += __shfl_xor_sync(0xffffffffu, a3, 8);
            a0 += __shfl_xor_sync(0xffffffffu, a0, 16);
            a1 += __shfl_xor_sync(0xffffffffu, a1, 16);
            a2 += __shfl_xor_sync(0xffffffffu, a2, 16);
            a3 += __shfl_xor_sync(0xffffffffu, a3, 16);
            if (lane < 8) {
                uint2 u2;
                u2.x = h2u(a0, a1);
                u2.y = h2u(a2, a3);
                *reinterpret_cast<uint2*>(g_acch + (size_t)gu * DHEAD + cq * 4) = u2;
            }
        }
    }
}

// ---------------------------------------------------------------------------
// Launch
// ---------------------------------------------------------------------------
extern "C" void kernel_launch(void* const* d_in, const int* in_sizes, int n_in,
                              void* d_out, int out_size)
{
    const float* query  = (const float*)d_in[0];
    const float* refp   = (const float*)d_in[1];
    const float* xin    = (const float*)d_in[2];
    const int*   shapes = (const int*)  d_in[3];
    const int*   lstart = (const int*)  d_in[4];
    const float* W_samp = (const float*)d_in[5];
    const float* b_samp = (const float*)d_in[6];
    const float* W_attn = (const float*)d_in[7];
    const float* b_attn = (const float*)d_in[8];
    const float* W_val  = (const float*)d_in[9];
    const float* b_val  = (const float*)d_in[10];
    const float* W_out  = (const float*)d_in[11];
    const float* b_out  = (const float*)d_in[12];
    float* out = (float*)d_out;

    const int Lq = in_sizes[0] / (BATCH * D_MODEL);
    const int M  = BATCH * Lq;

    void* pa;
    cudaGetSymbolAddress(&pa, g_attn);

    const int gx = (M + BM - 1) / BM;
    dim3 blk(256);
    const int n4 = M * 64;                   // M*256/4

    // 0) one-shot fp16 conversion + weight pack
    prep<<<1024, blk>>>(query, xin, W_val, W_out, W_samp, b_samp, W_attn, b_attn, n4);
    // 1) merged value + qk projection (value->fp16 remap; off->fp16; attn->f32)
    hgemm_vqk<<<dim3(gx, 5), blk>>>(b_val, (float*)pa, M, Lq);
    // 2) softmax + deformable sampling (writes fp16 acc)
    {
        const int total = M * NH;
        const int nblk  = (total + 15) / 16;
        msda_sample<<<nblk, blk>>>(refp, shapes, lstart, Lq, total);
    }
    // 3) output projection
    hgemm_out<<<dim3(gx, 2), blk>>>(b_out, out, M);
}